// round 4
// baseline (speedup 1.0000x reference)
#include <cuda_runtime.h>
#include <cstdint>

#define BB 8
#define NQ 1024
#define NKK 1024
#define DD 256
#define DVV 256
#define HH 64

// scratch (static device arrays: allocation-free)
__device__ float g_Tq[BB * HH * NQ];     // tanh(Qh), transposed [b][h][q]
__device__ float g_Tk[BB * NKK * HH];    // tanh(Kh), [b][k][h]
__device__ float g_S[(size_t)BB * NKK * NQ];  // scores/attn, k-major [b][k][q]

// ---------------- pass 1: projections + accurate tanh ----------------
// grid: 2*B*NQ/16 blocks, 64 threads (h). Each block does 16 rows sharing W reads.
__global__ __launch_bounds__(64) void proj_kernel(
    const float* __restrict__ Q, const float* __restrict__ K,
    const float* __restrict__ Wq, const float* __restrict__ Wk)
{
    __shared__ float xs[16 * DD];  // 16 rows of input, 16KB
    int blk = blockIdx.x;
    const int nQblocks = (BB * NQ) / 16;
    bool isK = blk >= nQblocks;
    int rb = isK ? blk - nQblocks : blk;
    int r0 = rb * 16;
    const float* X = (isK ? K : Q) + (size_t)r0 * DD;
    const float* W = isK ? Wk : Wq;
    int tid = threadIdx.x;

#pragma unroll
    for (int i = 0; i < 16; ++i)
        ((float4*)xs)[tid + i * 64] = ((const float4*)X)[tid + i * 64];
    __syncthreads();

    float acc[16];
#pragma unroll
    for (int r = 0; r < 16; ++r) acc[r] = 0.f;
    int h = tid;
#pragma unroll 4
    for (int d = 0; d < DD; ++d) {
        float w = W[d * HH + h];
#pragma unroll
        for (int r = 0; r < 16; ++r)
            acc[r] = fmaf(xs[r * DD + d], w, acc[r]);
    }
#pragma unroll
    for (int r = 0; r < 16; ++r) {
        float t = tanhf(acc[r]);          // accurate tanh (only 1M evals total)
        int row = r0 + r;                 // = b*1024 + n
        if (isK) {
            g_Tk[(size_t)row * HH + h] = t;               // coalesced over h
        } else {
            int b = row >> 10, q = row & 1023;
            g_Tq[((size_t)b * HH + h) * NQ + q] = t;      // transposed store
        }
    }
}

// ---------------- pass 2: scores via tanh identity (MUFU-bound) ----------------
// tanh(a+b)*wv = fma(wv,tb,wv*ta) * rcp(fma(ta,tb,1))
#define QT 128
#define KT 32
__global__ __launch_bounds__(128, 4) void score_kernel(
    const float* __restrict__ Wv, const int* __restrict__ vlen)
{
    __shared__ float sQ[HH * QT];   // [h][q], 32KB, conflict-free per-lane reads
    __shared__ float sK[KT * HH];   // [k][h], 8KB, broadcast reads
    __shared__ float sWv[HH];

    int b = blockIdx.y;
    int vl = vlen[b];
    int kbase = blockIdx.z * 64;
    if (kbase >= vl) return;        // structural skip of masked columns
    int q0 = blockIdx.x * QT;
    int tid = threadIdx.x;

    const float* tq = g_Tq + (size_t)b * HH * NQ + q0;
#pragma unroll
    for (int i = 0; i < (HH * QT) / 128; ++i) {
        int idx = tid + i * 128;
        int hh = idx >> 7, qq = idx & 127;
        sQ[idx] = tq[hh * NQ + qq];   // coalesced
    }
    if (tid < HH) sWv[tid] = Wv[tid];

    for (int t = 0; t < 2; ++t) {
        int k0 = kbase + t * KT;
        if (k0 >= vl) break;
        __syncthreads();
        const float* tk = g_Tk + ((size_t)b * NKK + k0) * HH;
#pragma unroll
        for (int i = 0; i < (KT * HH) / 128; ++i)
            sK[tid + i * 128] = tk[tid + i * 128];
        __syncthreads();

        for (int kc = 0; kc < KT; kc += 4) {
            float a0 = 0.f, a1 = 0.f, a2 = 0.f, a3 = 0.f;
#pragma unroll 8
            for (int h = 0; h < HH; ++h) {
                float ta = sQ[h * QT + tid];
                float wv = sWv[h];
                float wta = wv * ta;
                const float* kp = &sK[kc * HH + h];
                float tb0 = kp[0];
                float tb1 = kp[HH];
                float tb2 = kp[2 * HH];
                float tb3 = kp[3 * HH];
                float d0 = fmaf(ta, tb0, 1.f), n0 = fmaf(wv, tb0, wta);
                float d1 = fmaf(ta, tb1, 1.f), n1 = fmaf(wv, tb1, wta);
                float d2 = fmaf(ta, tb2, 1.f), n2 = fmaf(wv, tb2, wta);
                float d3 = fmaf(ta, tb3, 1.f), n3 = fmaf(wv, tb3, wta);
                float r0_, r1_, r2_, r3_;
                asm("rcp.approx.f32 %0, %1;" : "=f"(r0_) : "f"(d0));
                asm("rcp.approx.f32 %0, %1;" : "=f"(r1_) : "f"(d1));
                asm("rcp.approx.f32 %0, %1;" : "=f"(r2_) : "f"(d2));
                asm("rcp.approx.f32 %0, %1;" : "=f"(r3_) : "f"(d3));
                a0 = fmaf(n0, r0_, a0);
                a1 = fmaf(n1, r1_, a1);
                a2 = fmaf(n2, r2_, a2);
                a3 = fmaf(n3, r3_, a3);
            }
            float* sp = &g_S[((size_t)b * NKK + k0 + kc) * NQ + q0 + tid];
            if (k0 + kc + 0 < vl) sp[0] = a0;                 // coalesced over q
            if (k0 + kc + 1 < vl) sp[(size_t)NQ] = a1;
            if (k0 + kc + 2 < vl) sp[2 * (size_t)NQ] = a2;
            if (k0 + kc + 3 < vl) sp[3 * (size_t)NQ] = a3;
        }
    }
}

// ---------------- pass 3: masked softmax (no max pass: |score| <= ||Wv||_1 ~ 8) ----------------
__global__ __launch_bounds__(256) void softmax_kernel(const int* __restrict__ vlen)
{
    int b = blockIdx.y;
    int q = blockIdx.x * 256 + threadIdx.x;
    int vl = vlen[b];
    float* base = g_S + (size_t)b * NKK * NQ + q;
    float l = 0.f;
    for (int k = 0; k < vl; ++k)
        l += __expf(base[(size_t)k * NQ]);
    float inv = __fdividef(1.f, l);
    for (int k = 0; k < vl; ++k)
        base[(size_t)k * NQ] = __expf(base[(size_t)k * NQ]) * inv;
}

// ---------------- pass 4: out = attn @ V (fp32 tiled GEMM, FMA-bound) ----------------
#define GM 64
#define GN 64
#define GK 32
__global__ __launch_bounds__(256) void av_kernel(
    const float* __restrict__ V, const int* __restrict__ vlen,
    float* __restrict__ out)
{
    __shared__ float As[GK][GM + 4];
    __shared__ float Bs[GK][GN + 4];
    int b = blockIdx.z;
    int vl = vlen[b];
    int qb = blockIdx.x * GM;
    int vb = blockIdx.y * GN;
    int tid = threadIdx.x;
    int tx = tid & 15, ty = tid >> 4;

    float acc[4][4];
#pragma unroll
    for (int i = 0; i < 4; ++i)
#pragma unroll
        for (int j = 0; j < 4; ++j) acc[i][j] = 0.f;

    const float* Sb = g_S + (size_t)b * NKK * NQ;
    const float* Vb = V + (size_t)b * NKK * DVV;

    for (int k0 = 0; k0 < vl; k0 += GK) {
        __syncthreads();
#pragma unroll
        for (int i = 0; i < (GK * GM) / 256; ++i) {
            int idx = tid + i * 256;
            int kk = idx >> 6, cc = idx & 63;
            As[kk][cc] = (k0 + kk < vl) ? Sb[(size_t)(k0 + kk) * NQ + qb + cc] : 0.f;
            Bs[kk][cc] = Vb[(size_t)(k0 + kk) * DVV + vb + cc];
        }
        __syncthreads();
#pragma unroll
        for (int kk = 0; kk < GK; ++kk) {
            float4 av = *(const float4*)&As[kk][ty * 4];
            float4 bv = *(const float4*)&Bs[kk][tx * 4];
            acc[0][0] = fmaf(av.x, bv.x, acc[0][0]);
            acc[0][1] = fmaf(av.x, bv.y, acc[0][1]);
            acc[0][2] = fmaf(av.x, bv.z, acc[0][2]);
            acc[0][3] = fmaf(av.x, bv.w, acc[0][3]);
            acc[1][0] = fmaf(av.y, bv.x, acc[1][0]);
            acc[1][1] = fmaf(av.y, bv.y, acc[1][1]);
            acc[1][2] = fmaf(av.y, bv.z, acc[1][2]);
            acc[1][3] = fmaf(av.y, bv.w, acc[1][3]);
            acc[2][0] = fmaf(av.z, bv.x, acc[2][0]);
            acc[2][1] = fmaf(av.z, bv.y, acc[2][1]);
            acc[2][2] = fmaf(av.z, bv.z, acc[2][2]);
            acc[2][3] = fmaf(av.z, bv.w, acc[2][3]);
            acc[3][0] = fmaf(av.w, bv.x, acc[3][0]);
            acc[3][1] = fmaf(av.w, bv.y, acc[3][1]);
            acc[3][2] = fmaf(av.w, bv.z, acc[3][2]);
            acc[3][3] = fmaf(av.w, bv.w, acc[3][3]);
        }
    }
#pragma unroll
    for (int i = 0; i < 4; ++i) {
        float4 o;
        o.x = acc[i][0]; o.y = acc[i][1]; o.z = acc[i][2]; o.w = acc[i][3];
        *(float4*)&out[((size_t)b * NQ + qb + ty * 4 + i) * DVV + vb + tx * 4] = o;
    }
}

extern "C" void kernel_launch(void* const* d_in, const int* in_sizes, int n_in,
                              void* d_out, int out_size)
{
    const float* Q    = (const float*)d_in[0];
    const float* K    = (const float*)d_in[1];
    const float* V    = (const float*)d_in[2];
    const float* Wq   = (const float*)d_in[3];
    const float* Wk   = (const float*)d_in[4];
    const float* Wv   = (const float*)d_in[5];
    const int*   vlen = (const int*)d_in[6];
    float* out = (float*)d_out;

    proj_kernel<<<2 * BB * NQ / 16, 64>>>(Q, K, Wq, Wk);
    score_kernel<<<dim3(NQ / QT, BB, NKK / 64), 128>>>(Wv, vlen);
    softmax_kernel<<<dim3(NQ / 256, BB), 256>>>(vlen);
    av_kernel<<<dim3(NQ / GM, DVV / GN, BB), 256>>>(V, vlen, out);
}

// round 5
// speedup vs baseline: 1.3043x; 1.3043x over previous
#include <cuda_runtime.h>
#include <cstdint>

#define BB 8
#define NQ 1024
#define NKK 1024
#define DD 256
#define DVV 256
#define HH 64

// scratch (static device arrays: allocation-free)
__device__ float g_Tq[BB * HH * NQ];          // tanh(Qh), transposed [b][h][q]
__device__ float g_Tk[BB * NKK * HH];         // tanh(Kh), [b][k][h]
__device__ float g_S[(size_t)BB * NKK * NQ];  // exp(scores), k-major [b][k][q]
__device__ float g_Lp[16 * BB * NQ];          // partial row sums [z][b][q]
__device__ float g_Linv[BB * NQ];             // 1/rowsum

// ---------------- f32x2 packed helpers ----------------
__device__ __forceinline__ unsigned long long ffma2(unsigned long long a,
                                                    unsigned long long b,
                                                    unsigned long long c) {
    unsigned long long d;
    asm("fma.rn.f32x2 %0, %1, %2, %3;" : "=l"(d) : "l"(a), "l"(b), "l"(c));
    return d;
}
__device__ __forceinline__ unsigned long long mul2(unsigned long long a,
                                                   unsigned long long b) {
    unsigned long long d;
    asm("mul.rn.f32x2 %0, %1, %2;" : "=l"(d) : "l"(a), "l"(b));
    return d;
}
__device__ __forceinline__ unsigned long long pack2(float lo, float hi) {
    unsigned long long d;
    asm("mov.b64 %0, {%1, %2};" : "=l"(d) : "f"(lo), "f"(hi));
    return d;
}
__device__ __forceinline__ void unpack2(unsigned long long v, float& lo, float& hi) {
    asm("mov.b64 {%0, %1}, %2;" : "=f"(lo), "=f"(hi) : "l"(v));
}

// ---------------- pass 1: projections + accurate tanh ----------------
__global__ __launch_bounds__(64) void proj_kernel(
    const float* __restrict__ Q, const float* __restrict__ K,
    const float* __restrict__ Wq, const float* __restrict__ Wk)
{
    __shared__ float xs[16 * DD];
    int blk = blockIdx.x;
    const int nQblocks = (BB * NQ) / 16;
    bool isK = blk >= nQblocks;
    int rb = isK ? blk - nQblocks : blk;
    int r0 = rb * 16;
    const float* X = (isK ? K : Q) + (size_t)r0 * DD;
    const float* W = isK ? Wk : Wq;
    int tid = threadIdx.x;

#pragma unroll
    for (int i = 0; i < 16; ++i)
        ((float4*)xs)[tid + i * 64] = ((const float4*)X)[tid + i * 64];
    __syncthreads();

    float acc[16];
#pragma unroll
    for (int r = 0; r < 16; ++r) acc[r] = 0.f;
    int h = tid;
#pragma unroll 4
    for (int d = 0; d < DD; ++d) {
        float w = W[d * HH + h];
#pragma unroll
        for (int r = 0; r < 16; ++r)
            acc[r] = fmaf(xs[r * DD + d], w, acc[r]);
    }
#pragma unroll
    for (int r = 0; r < 16; ++r) {
        float t = tanhf(acc[r]);
        int row = r0 + r;
        if (isK) {
            g_Tk[(size_t)row * HH + h] = t;
        } else {
            int b = row >> 10, q = row & 1023;
            g_Tq[((size_t)b * HH + h) * NQ + q] = t;
        }
    }
}

// ---------------- pass 2: exp(scores) via tanh identity + partial row sums ----------------
// tanh(a+b)*wv = fma(wv,tb,wv*ta) * rcp(fma(ta,tb,1))
#define QT 128
#define KT 32
__global__ __launch_bounds__(128, 4) void score_kernel(
    const float* __restrict__ Wv, const int* __restrict__ vlen)
{
    __shared__ float sQ[HH * QT];
    __shared__ float sK[KT * HH];
    __shared__ float sWv[HH];

    int b = blockIdx.y;
    int vl = vlen[b];
    int kbase = blockIdx.z * 64;
    if (kbase >= vl) return;        // structural skip of masked columns
    int q0 = blockIdx.x * QT;
    int tid = threadIdx.x;

    const float* tq = g_Tq + (size_t)b * HH * NQ + q0;
#pragma unroll
    for (int i = 0; i < (HH * QT) / 128; ++i) {
        int idx = tid + i * 128;
        int hh = idx >> 7, qq = idx & 127;
        sQ[idx] = tq[hh * NQ + qq];
    }
    if (tid < HH) sWv[tid] = Wv[tid];

    float lsum = 0.f;

    for (int t = 0; t < 2; ++t) {
        int k0 = kbase + t * KT;
        if (k0 >= vl) break;
        __syncthreads();
        const float* tk = g_Tk + ((size_t)b * NKK + k0) * HH;
#pragma unroll
        for (int i = 0; i < (KT * HH) / 128; ++i)
            sK[tid + i * 128] = tk[tid + i * 128];
        __syncthreads();

        for (int kc = 0; kc < KT; kc += 4) {
            float a0 = 0.f, a1 = 0.f, a2 = 0.f, a3 = 0.f;
#pragma unroll 8
            for (int h = 0; h < HH; ++h) {
                float ta = sQ[h * QT + tid];
                float wv = sWv[h];
                float wta = wv * ta;
                const float* kp = &sK[kc * HH + h];
                float tb0 = kp[0];
                float tb1 = kp[HH];
                float tb2 = kp[2 * HH];
                float tb3 = kp[3 * HH];
                float d0 = fmaf(ta, tb0, 1.f), n0 = fmaf(wv, tb0, wta);
                float d1 = fmaf(ta, tb1, 1.f), n1 = fmaf(wv, tb1, wta);
                float d2 = fmaf(ta, tb2, 1.f), n2 = fmaf(wv, tb2, wta);
                float d3 = fmaf(ta, tb3, 1.f), n3 = fmaf(wv, tb3, wta);
                float r0_, r1_, r2_, r3_;
                asm("rcp.approx.f32 %0, %1;" : "=f"(r0_) : "f"(d0));
                asm("rcp.approx.f32 %0, %1;" : "=f"(r1_) : "f"(d1));
                asm("rcp.approx.f32 %0, %1;" : "=f"(r2_) : "f"(d2));
                asm("rcp.approx.f32 %0, %1;" : "=f"(r3_) : "f"(d3));
                a0 = fmaf(n0, r0_, a0);
                a1 = fmaf(n1, r1_, a1);
                a2 = fmaf(n2, r2_, a2);
                a3 = fmaf(n3, r3_, a3);
            }
            // exp here (scores bounded by ||Wv||_1, no max pass needed)
            float e0 = __expf(a0), e1 = __expf(a1), e2 = __expf(a2), e3 = __expf(a3);
            float* sp = &g_S[((size_t)b * NKK + k0 + kc) * NQ + q0 + tid];
            if (k0 + kc + 0 < vl) { sp[0] = e0;                 lsum += e0; }
            if (k0 + kc + 1 < vl) { sp[(size_t)NQ] = e1;        lsum += e1; }
            if (k0 + kc + 2 < vl) { sp[2 * (size_t)NQ] = e2;    lsum += e2; }
            if (k0 + kc + 3 < vl) { sp[3 * (size_t)NQ] = e3;    lsum += e3; }
        }
    }
    // deterministic partial row-sum (no float atomics)
    g_Lp[((size_t)blockIdx.z * BB + b) * NQ + q0 + tid] = lsum;
}

// ---------------- pass 3: fold partials -> 1/l (tiny) ----------------
__global__ __launch_bounds__(256) void reduce_l_kernel(const int* __restrict__ vlen)
{
    int b = blockIdx.y;
    int q = blockIdx.x * 256 + threadIdx.x;
    int vl = vlen[b];
    int nz = (vl + 63) >> 6;
    float l = 0.f;
    for (int z = 0; z < nz; ++z)
        l += g_Lp[((size_t)z * BB + b) * NQ + q];
    g_Linv[b * NQ + q] = __fdividef(1.f, l);
}

// ---------------- pass 4: out = (expS @ V) * (1/l), packed f32x2 FMA ----------------
#define GM 64
#define GN 64
#define GK 32
__global__ __launch_bounds__(256) void av_kernel(
    const float* __restrict__ V, const int* __restrict__ vlen,
    float* __restrict__ out)
{
    __shared__ float As[GK][GM];   // exp(scores), [k][q]
    __shared__ float Bs[GK][GN];   // V tile, [k][v]
    int b = blockIdx.z;
    int vl = vlen[b];
    int qb = blockIdx.x * GM;
    int vb = blockIdx.y * GN;
    int tid = threadIdx.x;
    int tx = tid & 15;   // v/4
    int ty = tid >> 4;   // q/4

    // acc[p][j]: q-pair p (rows ty*4+2p, ty*4+2p+1), column vb+tx*4+j
    unsigned long long acc[2][4];
#pragma unroll
    for (int p = 0; p < 2; ++p)
#pragma unroll
        for (int j = 0; j < 4; ++j) acc[p][j] = 0ULL;

    const float* Sb = g_S + (size_t)b * NKK * NQ;
    const float* Vb = V + (size_t)b * NKK * DVV;

    for (int k0 = 0; k0 < vl; k0 += GK) {
        __syncthreads();
#pragma unroll
        for (int i = 0; i < 2; ++i) {
            int lin = tid + i * 256;      // float4 index into [GK][GM]
            int kk = lin >> 4;            // 16 float4 per 64-float row
            int c4 = lin & 15;
            float4 a;
            if (k0 + kk < vl)
                a = *(const float4*)&Sb[(size_t)(k0 + kk) * NQ + qb + c4 * 4];
            else
                a = make_float4(0.f, 0.f, 0.f, 0.f);
            *(float4*)&As[kk][c4 * 4] = a;
            // k0+kk <= 1023 always (k0 <= 992, kk <= 31); V rows are valid memory
            *(float4*)&Bs[kk][c4 * 4] =
                *(const float4*)&Vb[(size_t)(k0 + kk) * DVV + vb + c4 * 4];
        }
        __syncthreads();
#pragma unroll
        for (int kk = 0; kk < GK; ++kk) {
            // A q-pairs loaded directly as 8-byte LDS (no pack needed)
            unsigned long long a01 = *(const unsigned long long*)&As[kk][ty * 4];
            unsigned long long a23 = *(const unsigned long long*)&As[kk][ty * 4 + 2];
            float4 bv = *(const float4*)&Bs[kk][tx * 4];
            unsigned long long b0 = pack2(bv.x, bv.x);
            unsigned long long b1 = pack2(bv.y, bv.y);
            unsigned long long b2 = pack2(bv.z, bv.z);
            unsigned long long b3 = pack2(bv.w, bv.w);
            acc[0][0] = ffma2(a01, b0, acc[0][0]);
            acc[0][1] = ffma2(a01, b1, acc[0][1]);
            acc[0][2] = ffma2(a01, b2, acc[0][2]);
            acc[0][3] = ffma2(a01, b3, acc[0][3]);
            acc[1][0] = ffma2(a23, b0, acc[1][0]);
            acc[1][1] = ffma2(a23, b1, acc[1][1]);
            acc[1][2] = ffma2(a23, b2, acc[1][2]);
            acc[1][3] = ffma2(a23, b3, acc[1][3]);
        }
    }

    // epilogue: multiply by 1/l per q row, then store
    const float* linv = g_Linv + b * NQ + qb + ty * 4;
    unsigned long long inv01 = pack2(linv[0], linv[1]);
    unsigned long long inv23 = pack2(linv[2], linv[3]);
#pragma unroll
    for (int p = 0; p < 2; ++p) {
        unsigned long long ip = (p == 0) ? inv01 : inv23;
        float lo[4], hi[4];
#pragma unroll
        for (int j = 0; j < 4; ++j) {
            unsigned long long r = mul2(acc[p][j], ip);
            unpack2(r, lo[j], hi[j]);
        }
        int row0 = qb + ty * 4 + 2 * p;
        float4 o;
        o.x = lo[0]; o.y = lo[1]; o.z = lo[2]; o.w = lo[3];
        *(float4*)&out[((size_t)b * NQ + row0) * DVV + vb + tx * 4] = o;
        o.x = hi[0]; o.y = hi[1]; o.z = hi[2]; o.w = hi[3];
        *(float4*)&out[((size_t)b * NQ + row0 + 1) * DVV + vb + tx * 4] = o;
    }
}

extern "C" void kernel_launch(void* const* d_in, const int* in_sizes, int n_in,
                              void* d_out, int out_size)
{
    const float* Q    = (const float*)d_in[0];
    const float* K    = (const float*)d_in[1];
    const float* V    = (const float*)d_in[2];
    const float* Wq   = (const float*)d_in[3];
    const float* Wk   = (const float*)d_in[4];
    const float* Wv   = (const float*)d_in[5];
    const int*   vlen = (const int*)d_in[6];
    float* out = (float*)d_out;

    proj_kernel<<<2 * BB * NQ / 16, 64>>>(Q, K, Wq, Wk);
    score_kernel<<<dim3(NQ / QT, BB, NKK / 64), 128>>>(Wv, vlen);
    reduce_l_kernel<<<dim3(NQ / 256, BB), 256>>>(vlen);
    av_kernel<<<dim3(NQ / GM, DVV / GN, BB), 256>>>(V, vlen, out);
}